// round 15
// baseline (speedup 1.0000x reference)
#include <cuda_runtime.h>

// CRF Viterbi decode: B=256, T=512, N=128. Output dtype = FLOAT32.
// R15 vs R12/R14: forward rebuilt with SCALAR FADD+FMNMX (no f32x2
// pack/unpack -> fma and alu pipes balanced ~256cyc each instead of
// alu-pipe oversubscription), and sorted placement pairing longest with
// shortest on the same SM (bid and bid+148 share an SM).
// Backward = R12 core (MLP-8 prefetch, 2-REDUX argmax, smem trT).

constexpr int NTAG = 128;
constexpr int TMAX = 512;
constexpr int BMAX = 256;
constexpr int TRS  = 132;   // padded smem row stride (floats) for trT

__device__ float g_hist[(long long)BMAX * TMAX * NTAG];  // 64 MB state history
__device__ int g_perm[3];      // [0]=logits idx, [1]=transitions idx, [2]=seqlen idx
__device__ int g_sorted[BMAX]; // g_sorted[rank] = seq index (desc by length)

__global__ void classify_kernel(const void* p0, const void* p1, const void* p2)
{
    const int tid = threadIdx.x;
    __shared__ int sL[BMAX];
    const void* ptrs[3] = {p0, p1, p2};

    if (tid == 0) {
        int seq_idx = -1;
        float meanabs[3];
        for (int k = 0; k < 3; ++k) {
            const int*   wi = (const int*)ptrs[k];
            const float* wf = (const float*)ptrs[k];
            bool all_len = true;
            float s = 0.0f;
            for (int i = 0; i < 64; ++i) {
                int v = wi[i];
                if (v < 1 || v > TMAX) all_len = false;
                s += fabsf(wf[i]);
            }
            meanabs[k] = s * (1.0f / 64.0f);
            if (all_len && seq_idx < 0) seq_idx = k;
        }
        if (seq_idx < 0) seq_idx = 2;

        int a = -1, c = -1;
        for (int k = 0; k < 3; ++k)
            if (k != seq_idx) { if (a < 0) a = k; else c = k; }
        int tr = (meanabs[a] < meanabs[c]) ? a : c;
        int lg = (tr == a) ? c : a;
        g_perm[0] = lg; g_perm[1] = tr; g_perm[2] = seq_idx;
    }
    __syncthreads();

    // Rank sequences by length (descending, ties by index) -> g_sorted.
    const int* seqlen = (const int*)ptrs[g_perm[2]];
    int Li = seqlen[tid];
    if (Li < 1) Li = 1;
    if (Li > TMAX) Li = TMAX;
    sL[tid] = Li;
    __syncthreads();

    int r = 0;
    for (int k = 0; k < BMAX; ++k) {
        int Lk = sL[k];
        r += (Lk > Li) || (Lk == Li && k < tid);
    }
    g_sorted[r] = tid;
}

// Monotone order-preserving float->uint (equal floats -> equal uints).
__device__ __forceinline__ unsigned ordered_u32(float f) {
    unsigned u = __float_as_uint(f);
    return ((int)u >= 0) ? (u | 0x80000000u) : ~u;
}

__global__ void __launch_bounds__(128)
crf_fused_kernel(const void* p0, const void* p1, const void* p2,
                 float* __restrict__ out)
{
    const void* ptrs[3] = {p0, p1, p2};
    const float* logits = (const float*)ptrs[g_perm[0]];
    const float* trans  = (const float*)ptrs[g_perm[1]];
    const int*   seqlen = (const int*)ptrs[g_perm[2]];

    extern __shared__ __align__(16) float dsm[];
    float* st    = dsm;             // 2 * NTAG state double buffer
    float* sm_tr = dsm + 2 * NTAG;  // sm_tr[j*TRS+i] = trans[i][j]

    // Placement-aware pairing: bid and bid+148 land on the same SM
    // (classic modular bid->SM map). Pair rank c with rank 255-c.
    const int bid = blockIdx.x;
    const int rank = (bid < 148) ? bid : (403 - bid);
    const int b = g_sorted[rank];

    const int j = threadIdx.x;

    // Transition column j in registers (scalar); transposed copy into smem.
    float trc[NTAG];
#pragma unroll
    for (int n = 0; n < NTAG; ++n)
        trc[n] = trans[n * NTAG + j];
#pragma unroll
    for (int m = 0; m < 64; ++m)
        *(float2*)(sm_tr + j * TRS + 2 * m) = make_float2(trc[2 * m], trc[2 * m + 1]);

    const float* lg = logits + (long long)b * TMAX * NTAG;
    float* hist = g_hist + (long long)b * TMAX * NTAG;

    int L = seqlen[b];
    if (L < 1) L = 1;
    if (L > TMAX) L = TMAX;

    float s0 = lg[j];
    st[j] = s0;
    hist[j] = s0;
    __syncthreads();

    // ---- Forward: scalar FADD + FMNMX, 8 independent chains ----
    for (int t = 1; t < L; ++t) {
        const float x = lg[t * NTAG + j];
        const float4* s4 = (const float4*)(st + ((t - 1) & 1) * NTAG);

        float best[8];
#pragma unroll
        for (int k = 0; k < 8; ++k) best[k] = -3.402823466e38f;

#pragma unroll
        for (int k = 0; k < 8; ++k) {
#pragma unroll
            for (int q = 0; q < 4; ++q) {
                float4 s = s4[k * 4 + q];
                const int nb = k * 16 + q * 4;
                best[k] = fmaxf(best[k], s.x + trc[nb + 0]);
                best[k] = fmaxf(best[k], s.y + trc[nb + 1]);
                best[k] = fmaxf(best[k], s.z + trc[nb + 2]);
                best[k] = fmaxf(best[k], s.w + trc[nb + 3]);
            }
        }

        // Max tree (no tie info needed in forward).
        float m0 = fmaxf(best[0], best[1]);
        float m1 = fmaxf(best[2], best[3]);
        float m2 = fmaxf(best[4], best[5]);
        float m3 = fmaxf(best[6], best[7]);
        float bb = fmaxf(fmaxf(m0, m1), fmaxf(m2, m3));

        float nv = bb + x;
        st[(t & 1) * NTAG + j] = nv;
        hist[t * NTAG + j] = nv;
        __syncthreads();
    }

    // Zero masked tail [L, T) — float output, d_out poisoned.
    float* orow = out + b * TMAX;
    for (int p = L + j; p < TMAX; p += NTAG)
        orow[p] = 0.0f;

    // ---- Backward: warp 0 backtraces this sequence ----
    if (j < 32) {
        const int lane = j;
        const int i0 = lane * 4;
        const float* fs = st + ((L - 1) & 1) * NTAG;
        int cur;

        auto wargmax = [&](float v0, float v1, float v2, float v3) -> int {
            float best = v0; int lidx = 0; bool p;
            p = v1 > best; best = p ? v1 : best; lidx = p ? 1 : lidx;
            p = v2 > best; best = p ? v2 : best; lidx = p ? 2 : lidx;
            p = v3 > best; best = p ? v3 : best; lidx = p ? 3 : lidx;
            unsigned ub = ordered_u32(best);
            unsigned wm = __reduce_max_sync(0xFFFFFFFFu, ub);
            unsigned gi = (ub == wm) ? (unsigned)(i0 + lidx) : 0xFFFFFFFFu;
            return (int)__reduce_min_sync(0xFFFFFFFFu, gi);
        };

        {
            float4 h = *(const float4*)(fs + i0);
            cur = wargmax(h.x, h.y, h.z, h.w);
            if (lane == 0) orow[L - 1] = (float)cur;
        }

        auto step = [&](float4 hh, int tt) {
            float4 tv = *(const float4*)(sm_tr + cur * TRS + i0);
            cur = wargmax(hh.x + tv.x, hh.y + tv.y, hh.z + tv.z, hh.w + tv.w);
            if (lane == 0) orow[tt - 1] = (float)cur;
        };

        float4 bufA[8], bufB[8];
        auto load8 = [&](float4 (&buf)[8], int tb) {
#pragma unroll
            for (int k = 0; k < 8; ++k) {
                int rr = tb - 1 - k;
                rr = (rr >= 0) ? rr : 0;
                buf[k] = *(const float4*)(hist + rr * NTAG + i0);
            }
        };

        int t = L - 1;
        if (t >= 1) {
            load8(bufA, t);
            while (true) {
                load8(bufB, t - 8);
#pragma unroll
                for (int k = 0; k < 8; ++k)
                    if (t - k >= 1) step(bufA[k], t - k);
                t -= 8;
                if (t < 1) break;

                load8(bufA, t - 8);
#pragma unroll
                for (int k = 0; k < 8; ++k)
                    if (t - k >= 1) step(bufB[k], t - k);
                t -= 8;
                if (t < 1) break;
            }
        }
    }
}

extern "C" void kernel_launch(void* const* d_in, const int* in_sizes, int n_in,
                              void* d_out, int out_size) {
    (void)in_sizes; (void)out_size;
    const void* p0 = d_in[0];
    const void* p1 = (n_in > 1) ? d_in[1] : d_in[0];
    const void* p2 = (n_in > 2) ? d_in[2] : d_in[0];
    float* out = (float*)d_out;

    const int smem_bytes = (2 * NTAG + NTAG * TRS) * 4;   // 68608
    cudaFuncSetAttribute(crf_fused_kernel,
                         cudaFuncAttributeMaxDynamicSharedMemorySize, smem_bytes);

    classify_kernel<<<1, BMAX>>>(p0, p1, p2);
    crf_fused_kernel<<<BMAX, NTAG, smem_bytes>>>(p0, p1, p2, out);
}

// round 16
// speedup vs baseline: 1.1746x; 1.1746x over previous
#include <cuda_runtime.h>

// CRF Viterbi decode: B=256, T=512, N=128. Output dtype = FLOAT32.
// R16: R12 f32x2 forward core (proven fastest) + persistent work-stealing at
// 2 CTAs/SM (grid=296; co-resident CTAs self-balance by pulling longest-first
// ranks from an atomic counter) + logits prefetched 2 steps deep so the DRAM
// LDG is never exposed. Backward = R12 (MLP-8 prefetch, 2-REDUX argmax).

constexpr int NTAG = 128;
constexpr int TMAX = 512;
constexpr int BMAX = 256;
constexpr int TRS  = 132;   // padded smem row stride (floats) for trT
constexpr int NSM  = 148;

__device__ float g_hist[(long long)BMAX * TMAX * NTAG];  // 64 MB state history
__device__ int g_perm[3];      // [0]=logits idx, [1]=transitions idx, [2]=seqlen idx
__device__ int g_sorted[BMAX]; // g_sorted[rank] = seq index (desc by length)
__device__ int g_work;         // work counter (reset by classify each replay)

#define ADD_F32X2(out, a, b) \
    asm("add.rn.f32x2 %0, %1, %2;" : "=l"(out) : "l"(a), "l"(b))
#define PACK_F32X2(out, lo, hi) \
    asm("mov.b64 %0, {%1, %2};" : "=l"(out) : "r"(lo), "r"(hi))
#define UNPACK_F32X2(lo, hi, in) \
    asm("mov.b64 {%0, %1}, %2;" : "=r"(lo), "=r"(hi) : "l"(in))

__global__ void classify_kernel(const void* p0, const void* p1, const void* p2)
{
    const int tid = threadIdx.x;
    __shared__ int sL[BMAX];
    const void* ptrs[3] = {p0, p1, p2};

    if (tid == 0) {
        g_work = 0;                       // reset work counter every replay
        int seq_idx = -1;
        float meanabs[3];
        for (int k = 0; k < 3; ++k) {
            const int*   wi = (const int*)ptrs[k];
            const float* wf = (const float*)ptrs[k];
            bool all_len = true;
            float s = 0.0f;
            for (int i = 0; i < 64; ++i) {
                int v = wi[i];
                if (v < 1 || v > TMAX) all_len = false;
                s += fabsf(wf[i]);
            }
            meanabs[k] = s * (1.0f / 64.0f);
            if (all_len && seq_idx < 0) seq_idx = k;
        }
        if (seq_idx < 0) seq_idx = 2;

        int a = -1, c = -1;
        for (int k = 0; k < 3; ++k)
            if (k != seq_idx) { if (a < 0) a = k; else c = k; }
        int tr = (meanabs[a] < meanabs[c]) ? a : c;
        int lg = (tr == a) ? c : a;
        g_perm[0] = lg; g_perm[1] = tr; g_perm[2] = seq_idx;
    }
    __syncthreads();

    // Rank sequences by length (descending, ties by index) -> g_sorted.
    const int* seqlen = (const int*)ptrs[g_perm[2]];
    int Li = seqlen[tid];
    if (Li < 1) Li = 1;
    if (Li > TMAX) Li = TMAX;
    sL[tid] = Li;
    __syncthreads();

    int r = 0;
    for (int k = 0; k < BMAX; ++k) {
        int Lk = sL[k];
        r += (Lk > Li) || (Lk == Li && k < tid);
    }
    g_sorted[r] = tid;
}

// Monotone order-preserving float->uint (equal floats -> equal uints).
__device__ __forceinline__ unsigned ordered_u32(float f) {
    unsigned u = __float_as_uint(f);
    return ((int)u >= 0) ? (u | 0x80000000u) : ~u;
}

__global__ void __launch_bounds__(128, 2)
crf_fused_kernel(const void* p0, const void* p1, const void* p2,
                 float* __restrict__ out)
{
    const void* ptrs[3] = {p0, p1, p2};
    const float* logits = (const float*)ptrs[g_perm[0]];
    const float* trans  = (const float*)ptrs[g_perm[1]];
    const int*   seqlen = (const int*)ptrs[g_perm[2]];

    extern __shared__ __align__(16) float dsm[];
    float* st    = dsm;             // 2 * NTAG state double buffer
    float* sm_tr = dsm + 2 * NTAG;  // sm_tr[j*TRS+i] = trans[i][j]
    __shared__ int s_rank;

    const int j = threadIdx.x;

    // Transition column j packed into 64 x f32x2, transposed into smem. Once.
    unsigned long long trp[64];
#pragma unroll
    for (int m = 0; m < 64; ++m) {
        unsigned int lo = __float_as_uint(trans[(2 * m) * NTAG + j]);
        unsigned int hi = __float_as_uint(trans[(2 * m + 1) * NTAG + j]);
        PACK_F32X2(trp[m], lo, hi);
        *(float2*)(sm_tr + j * TRS + 2 * m) =
            make_float2(__uint_as_float(lo), __uint_as_float(hi));
    }

    while (true) {
        __syncthreads();                 // protects s_rank + st reuse
        if (j == 0) s_rank = atomicAdd(&g_work, 1);
        __syncthreads();
        const int r = s_rank;
        if (r >= BMAX) break;            // uniform across CTA

        const int b = g_sorted[r];       // longest-first
        const float* lg = logits + (long long)b * TMAX * NTAG;
        float* hist = g_hist + (long long)b * TMAX * NTAG;

        int L = seqlen[b];
        if (L < 1) L = 1;
        if (L > TMAX) L = TMAX;

        float s0 = lg[j];
        st[j] = s0;
        hist[j] = s0;

        // Logits prefetch, depth 2 (row index clamped; rows < TMAX always).
        float x_cur = lg[NTAG + j];                       // t = 1
        float x_nxt = lg[(2 < TMAX ? 2 : TMAX - 1) * NTAG + j];
        __syncthreads();

        // ---- Forward: max-only, packed f32x2 adds, 8 FMNMX chains ----
        for (int t = 1; t < L; ++t) {
            const float x = x_cur;
            x_cur = x_nxt;
            int tn = t + 2; tn = (tn < TMAX) ? tn : (TMAX - 1);
            x_nxt = lg[tn * NTAG + j];

            const ulonglong2* s2 = (const ulonglong2*)(st + ((t - 1) & 1) * NTAG);

            float best[8];
#pragma unroll
            for (int k = 0; k < 8; ++k) best[k] = -3.402823466e38f;

#pragma unroll
            for (int k = 0; k < 8; ++k) {
#pragma unroll
                for (int q = 0; q < 4; ++q) {
                    ulonglong2 u = s2[k * 4 + q];
                    unsigned long long r0, r1;
                    ADD_F32X2(r0, u.x, trp[k * 8 + q * 2]);
                    ADD_F32X2(r1, u.y, trp[k * 8 + q * 2 + 1]);
                    unsigned int a0, a1, b0, b1;
                    UNPACK_F32X2(a0, a1, r0);
                    UNPACK_F32X2(b0, b1, r1);
                    best[k] = fmaxf(best[k], __uint_as_float(a0));
                    best[k] = fmaxf(best[k], __uint_as_float(a1));
                    best[k] = fmaxf(best[k], __uint_as_float(b0));
                    best[k] = fmaxf(best[k], __uint_as_float(b1));
                }
            }

            float bb = best[0];
#pragma unroll
            for (int k = 1; k < 8; ++k) bb = fmaxf(bb, best[k]);

            float nv = bb + x;
            st[(t & 1) * NTAG + j] = nv;
            hist[t * NTAG + j] = nv;
            __syncthreads();
        }

        // Zero masked tail [L, T) — float output, d_out poisoned.
        float* orow = out + b * TMAX;
        for (int p = L + j; p < TMAX; p += NTAG)
            orow[p] = 0.0f;

        // ---- Backward: warp 0 backtraces this sequence ----
        if (j < 32) {
            const int lane = j;
            const int i0 = lane * 4;
            const float* fs = st + ((L - 1) & 1) * NTAG;
            int cur;

            auto wargmax = [&](float v0, float v1, float v2, float v3) -> int {
                float best = v0; int lidx = 0; bool p;
                p = v1 > best; best = p ? v1 : best; lidx = p ? 1 : lidx;
                p = v2 > best; best = p ? v2 : best; lidx = p ? 2 : lidx;
                p = v3 > best; best = p ? v3 : best; lidx = p ? 3 : lidx;
                unsigned ub = ordered_u32(best);
                unsigned wm = __reduce_max_sync(0xFFFFFFFFu, ub);
                unsigned gi = (ub == wm) ? (unsigned)(i0 + lidx) : 0xFFFFFFFFu;
                return (int)__reduce_min_sync(0xFFFFFFFFu, gi);
            };

            {
                float4 h = *(const float4*)(fs + i0);
                cur = wargmax(h.x, h.y, h.z, h.w);
                if (lane == 0) orow[L - 1] = (float)cur;
            }

            auto step = [&](float4 hh, int tt) {
                float4 tv = *(const float4*)(sm_tr + cur * TRS + i0);
                cur = wargmax(hh.x + tv.x, hh.y + tv.y, hh.z + tv.z, hh.w + tv.w);
                if (lane == 0) orow[tt - 1] = (float)cur;
            };

            float4 bufA[8], bufB[8];
            auto load8 = [&](float4 (&buf)[8], int tb) {
#pragma unroll
                for (int k = 0; k < 8; ++k) {
                    int rr = tb - 1 - k;
                    rr = (rr >= 0) ? rr : 0;
                    buf[k] = *(const float4*)(hist + rr * NTAG + i0);
                }
            };

            int t = L - 1;
            if (t >= 1) {
                load8(bufA, t);
                while (true) {
                    load8(bufB, t - 8);
#pragma unroll
                    for (int k = 0; k < 8; ++k)
                        if (t - k >= 1) step(bufA[k], t - k);
                    t -= 8;
                    if (t < 1) break;

                    load8(bufA, t - 8);
#pragma unroll
                    for (int k = 0; k < 8; ++k)
                        if (t - k >= 1) step(bufB[k], t - k);
                    t -= 8;
                    if (t < 1) break;
                }
            }
        }
    }
}

extern "C" void kernel_launch(void* const* d_in, const int* in_sizes, int n_in,
                              void* d_out, int out_size) {
    (void)in_sizes; (void)out_size;
    const void* p0 = d_in[0];
    const void* p1 = (n_in > 1) ? d_in[1] : d_in[0];
    const void* p2 = (n_in > 2) ? d_in[2] : d_in[0];
    float* out = (float*)d_out;

    const int smem_bytes = (2 * NTAG + NTAG * TRS) * 4;   // 68608
    cudaFuncSetAttribute(crf_fused_kernel,
                         cudaFuncAttributeMaxDynamicSharedMemorySize, smem_bytes);

    classify_kernel<<<1, BMAX>>>(p0, p1, p2);
    crf_fused_kernel<<<2 * NSM, NTAG, smem_bytes>>>(p0, p1, p2, out);
}